// round 3
// baseline (speedup 1.0000x reference)
#include <cuda_runtime.h>
#include <cuda_bf16.h>

#define Bb 4
#define Nn 2048
#define Ff 256
#define Tt 8
#define Hh 4
#define Dd 64
#define FT 264
#define BH (Bb*Hh)      // 16
#define BHN (BH*Nn)     // 32768

// ---- scratch (static device globals; no allocation) ----
__device__ float g_v1[Hh*FT];
__device__ float g_v2[Hh*FT];
__device__ float g_u[BHN];    // e1 per (b,h,i)
__device__ float g_E1[BHN];   // exp(e1)
__device__ float g_F1[BHN];   // exp(0.2*e1)
__device__ float g_vv[BHN];   // e2 per (b,h,j)
__device__ float g_SE[BHN];
__device__ float g_SF[BHN];
__device__ float g_c1[BHN];
__device__ float g_c2[BHN];
__device__ float g_Wh[BH*Nn*Dd]; // 8MB: Wh[b][h][n][d]

// ---- K0: v1[h][f] = sum_d Wq[h,f,d]*a1[h,d]; v2 likewise with Wk,a2 ----
__global__ void k0_v(const float* __restrict__ Wq, const float* __restrict__ Wk,
                     const float* __restrict__ a){
  int idx = blockIdx.x*blockDim.x + threadIdx.x;
  if (idx >= Hh*FT) return;
  int h = idx / FT, f = idx - h*FT;
  const float* wq = Wq + (h*FT + f)*Dd;
  const float* wk = Wk + (h*FT + f)*Dd;
  const float* a1 = a + h*2*Dd;
  const float* a2 = a1 + Dd;
  float s1 = 0.f, s2 = 0.f;
  #pragma unroll
  for (int d = 0; d < Dd; d++){ s1 += wq[d]*a1[d]; s2 += wk[d]*a2[d]; }
  g_v1[idx] = s1; g_v2[idx] = s2;
}

// ---- zero the accumulator scratch (must run every launch: graph replays) ----
__global__ void k_init(){
  int idx = blockIdx.x*blockDim.x + threadIdx.x;
  if (idx < BHN){ g_SE[idx] = 0.f; g_SF[idx] = 0.f; }
}

// ---- K1: Wh[b,h,n,d] = sum_f x[b,n,f] * W[h,f,d]  (8192x256 @ 256x256) ----
__global__ void __launch_bounds__(256) k1_wh(const float* __restrict__ x,
                                             const float* __restrict__ W){
  __shared__ float Xs[16][68];
  __shared__ float Ws[16][68];
  int m0 = blockIdx.x*64;
  int h  = blockIdx.y;
  int tid = threadIdx.x;
  int tx = tid & 15, ty = tid >> 4;
  int lm = tid >> 2;            // 0..63
  int lk = (tid & 3) * 4;       // 0,4,8,12
  int wkk = tid >> 4;           // 0..15
  int wc  = (tid & 15) * 4;     // 0..60
  float acc[4][4];
  #pragma unroll
  for (int i=0;i<4;i++)
    #pragma unroll
    for (int j=0;j<4;j++) acc[i][j]=0.f;

  for (int k0 = 0; k0 < Ff; k0 += 16){
    float4 xv = *(const float4*)&x[(m0+lm)*Ff + k0 + lk];
    Xs[lk+0][lm]=xv.x; Xs[lk+1][lm]=xv.y; Xs[lk+2][lm]=xv.z; Xs[lk+3][lm]=xv.w;
    *(float4*)&Ws[wkk][wc] = *(const float4*)&W[h*Ff*Dd + (k0+wkk)*Dd + wc];
    __syncthreads();
    #pragma unroll
    for (int k=0;k<16;k++){
      float4 a4 = *(float4*)&Xs[k][ty*4];
      float4 b4 = *(float4*)&Ws[k][tx*4];
      float av[4] = {a4.x,a4.y,a4.z,a4.w};
      float bv[4] = {b4.x,b4.y,b4.z,b4.w};
      #pragma unroll
      for (int i=0;i<4;i++)
        #pragma unroll
        for (int j=0;j<4;j++) acc[i][j] += av[i]*bv[j];
    }
    __syncthreads();
  }
  #pragma unroll
  for (int i=0;i<4;i++){
    int m = m0 + ty*4 + i;
    int b = m >> 11, n = m & (Nn-1);
    float4 o = make_float4(acc[i][0],acc[i][1],acc[i][2],acc[i][3]);
    *(float4*)&g_Wh[((b*Hh+h)*Nn + n)*Dd + tx*4] = o;
  }
}

// ---- K1b: e1/e2 GEMVs; one warp per node ----
__global__ void __launch_bounds__(256) k1b_e(const float* __restrict__ x,
                                             const float* __restrict__ toh){
  __shared__ float sv1[Hh*FT], sv2[Hh*FT];
  int tid = threadIdx.x;
  for (int i = tid; i < Hh*FT; i += 256){ sv1[i]=g_v1[i]; sv2[i]=g_v2[i]; }
  __syncthreads();
  int warp = tid >> 5, lane = tid & 31;
  int node = blockIdx.x*8 + warp;
  int b = node >> 11, n = node & (Nn-1);
  const float* xr = x + node*Ff;
  float aq[4]={0,0,0,0}, ak[4]={0,0,0,0};
  for (int f0 = 0; f0 < Ff; f0 += 32){
    float xv = xr[f0+lane];
    #pragma unroll
    for (int h=0;h<4;h++){
      aq[h] += xv * sv1[h*FT + f0 + lane];
      ak[h] += xv * sv2[h*FT + f0 + lane];
    }
  }
  if (lane < Tt){
    float tv = toh[node*Tt + lane];
    #pragma unroll
    for (int h=0;h<4;h++){
      aq[h] += tv * sv1[h*FT + Ff + lane];
      ak[h] += tv * sv2[h*FT + Ff + lane];
    }
  }
  #pragma unroll
  for (int off=16; off; off>>=1){
    #pragma unroll
    for (int h=0;h<4;h++){
      aq[h] += __shfl_xor_sync(0xffffffffu, aq[h], off);
      ak[h] += __shfl_xor_sync(0xffffffffu, ak[h], off);
    }
  }
  if (lane == 0){
    #pragma unroll
    for (int h=0;h<4;h++){
      int idx = (b*Hh + h)*Nn + n;
      g_u[idx]  = aq[h];
      g_E1[idx] = __expf(aq[h]);
      g_F1[idx] = __expf(0.2f*aq[h]);
      g_vv[idx] = ak[h];
    }
  }
}

// ---- K2: column stats. SE[j] = sum_{adj, u_i+v_j>0} E1[i]; SF analog ----
__global__ void __launch_bounds__(256) k2_stats(const int* __restrict__ adj){
  __shared__ float su[1024], sE[1024], sF[1024];
  int tid = threadIdx.x;
  int jt = blockIdx.x, ic = blockIdx.y, b = blockIdx.z;
  int i0 = ic*256;
  for (int i = tid; i < 1024; i += 256){
    int h = i >> 8, ii = i & 255;
    int idx = (b*Hh + h)*Nn + i0 + ii;
    su[i] = g_u[idx]; sE[i] = g_E1[idx]; sF[i] = g_F1[idx];
  }
  __syncthreads();
  int j = jt*256 + tid;
  float v4[4], SEr[4]={0,0,0,0}, SFr[4]={0,0,0,0};
  #pragma unroll
  for (int h=0;h<4;h++) v4[h] = g_vv[(b*Hh+h)*Nn + j];
  const int* ap = adj + (b*Nn + i0)*Nn + j;
  #pragma unroll 4
  for (int ii = 0; ii < 256; ii++){
    int aj = ap[ii*Nn];
    if (aj){
      #pragma unroll
      for (int h=0;h<4;h++){
        bool pos = (su[h*256+ii] + v4[h]) > 0.f;
        SEr[h] += pos ? sE[h*256+ii] : 0.f;
        SFr[h] += pos ? 0.f : sF[h*256+ii];
      }
    }
  }
  #pragma unroll
  for (int h=0;h<4;h++){
    atomicAdd(&g_SE[(b*Hh+h)*Nn + j], SEr[h]);
    atomicAdd(&g_SF[(b*Hh+h)*Nn + j], SFr[h]);
  }
}

// ---- K2b: per-column coefficients c1,c2 ----
__global__ void k2b_c(){
  int idx = blockIdx.x*blockDim.x + threadIdx.x;
  if (idx >= BHN) return;
  float v  = g_vv[idx];
  float ev = __expf(v), ef = __expf(0.2f*v);
  float den = ev*g_SE[idx] + ef*g_SF[idx];
  float inv = (den > 0.f) ? (1.f/den) : 0.f;
  g_c1[idx] = ev*inv;
  g_c2[idx] = ef*inv;
}

// ---- K3: out[b,n,h*64+d] = elu( sum_j P[i,j]*Wh[j,d] ), P built on the fly ----
// Tile: 128 i x 32 j x 64 d. Block 256 threads, 8x4 register tile per thread.
__global__ void __launch_bounds__(256) k3_agg(const int* __restrict__ adj,
                                              float* __restrict__ out){
  __shared__ float Ps[32][132];   // [jj][ii], pad 132: float4-aligned, conflict-free
  __shared__ float Whs[32][68];   // [jj][d]
  __shared__ float su[128], sE1[128], sF1[128];
  int b = blockIdx.z, h = blockIdx.y, i0 = blockIdx.x*128;
  int bh = b*Hh + h;
  int tid = threadIdx.x;
  if (tid < 128){
    int idx = bh*Nn + i0 + tid;
    su[tid]=g_u[idx]; sE1[tid]=g_E1[idx]; sF1[tid]=g_F1[idx];
  }
  int jj  = tid & 31, iiq = tid >> 5;   // phase A: 8 groups of 16 i each
  int tx  = tid & 15, ty  = tid >> 4;   // phase B: 16 d-groups x 16 i-groups
  int wkk = tid >> 3;                   // 0..31 (Wh row)
  int wd  = (tid & 7) * 8;              // 0..56
  float acc[8][4];
  #pragma unroll
  for (int r=0;r<8;r++)
    #pragma unroll
    for (int c=0;c<4;c++) acc[r][c]=0.f;
  __syncthreads();

  for (int j0 = 0; j0 < Nn; j0 += 32){
    float vj = g_vv[bh*Nn + j0 + jj];
    float c1 = g_c1[bh*Nn + j0 + jj];
    float c2 = g_c2[bh*Nn + j0 + jj];
    const int* ap = adj + (b*Nn + i0 + iiq*16)*Nn + j0 + jj;
    // phase A: build P tile (16 entries per thread, float4 stores)
    #pragma unroll
    for (int q=0;q<4;q++){
      float p[4];
      #pragma unroll
      for (int r=0;r<4;r++){
        int ii = iiq*16 + q*4 + r;
        int aj = ap[(q*4+r)*Nn];
        float s = su[ii] + vj;
        float val = (s > 0.f) ? sE1[ii]*c1 : sF1[ii]*c2;
        p[r] = aj ? val : 0.f;
      }
      *(float4*)&Ps[jj][iiq*16 + q*4] = make_float4(p[0],p[1],p[2],p[3]);
    }
    // stage Wh tile
    {
      const float* wp = &g_Wh[(bh*Nn + j0 + wkk)*Dd + wd];
      float4 w0 = *(const float4*)(wp+0);
      float4 w1 = *(const float4*)(wp+4);
      *(float4*)&Whs[wkk][wd+0] = w0;
      *(float4*)&Whs[wkk][wd+4] = w1;
    }
    __syncthreads();
    // phase B: 8x4 register-tile GEMM over k=32
    #pragma unroll 16
    for (int k=0;k<32;k++){
      float4 a0 = *(float4*)&Ps[k][ty*8];
      float4 a1 = *(float4*)&Ps[k][ty*8+4];
      float4 b4 = *(float4*)&Whs[k][tx*4];
      float av[8] = {a0.x,a0.y,a0.z,a0.w,a1.x,a1.y,a1.z,a1.w};
      float bv[4] = {b4.x,b4.y,b4.z,b4.w};
      #pragma unroll
      for (int r=0;r<8;r++)
        #pragma unroll
        for (int c=0;c<4;c++) acc[r][c] += av[r]*bv[c];
    }
    __syncthreads();
  }
  // epilogue: ELU + write out[b][n][h*64 + d]
  #pragma unroll
  for (int r=0;r<8;r++){
    int n = i0 + ty*8 + r;
    float t; float4 o;
    t = acc[r][0]; o.x = (t > 0.f) ? t : (__expf(t)-1.f);
    t = acc[r][1]; o.y = (t > 0.f) ? t : (__expf(t)-1.f);
    t = acc[r][2]; o.z = (t > 0.f) ? t : (__expf(t)-1.f);
    t = acc[r][3]; o.w = (t > 0.f) ? t : (__expf(t)-1.f);
    *(float4*)&out[(b*Nn + n)*(Hh*Dd) + h*Dd + tx*4] = o;
  }
}

extern "C" void kernel_launch(void* const* d_in, const int* in_sizes, int n_in,
                              void* d_out, int out_size) {
  const float* x   = (const float*)d_in[0];  // (4,2048,256)
  const int*   adj = (const int*)  d_in[1];  // (4,2048,2048)
  const float* toh = (const float*)d_in[2];  // (4,2048,8)
  const float* Wq  = (const float*)d_in[3];  // (4,264,64)
  const float* Wk  = (const float*)d_in[4];  // (4,264,64)
  const float* W   = (const float*)d_in[5];  // (4,256,64)
  const float* a   = (const float*)d_in[6];  // (4,128,1)
  float* out = (float*)d_out;                // (4,2048,1024) fp32

  k0_v<<<5, 256>>>(Wq, Wk, a);
  k_init<<<128, 256>>>();
  k1_wh<<<dim3(128, 4), 256>>>(x, W);
  k1b_e<<<1024, 256>>>(x, toh);
  k2_stats<<<dim3(8, 8, 4), 256>>>(adj);
  k2b_c<<<128, 256>>>();
  k3_agg<<<dim3(16, 4, 4), 256>>>(adj, out);
}

// round 6
// speedup vs baseline: 1.8784x; 1.8784x over previous
#include <cuda_runtime.h>
#include <cuda_bf16.h>
#include <cstdint>

#define Bb 4
#define Nn 2048
#define Ff 256
#define Tt 8
#define Hh 4
#define Dd 64
#define FT 264
#define BH (Bb*Hh)      // 16
#define BHN (BH*Nn)     // 32768

// ---- scratch (static device globals; no allocation) ----
__device__ float g_v1[Hh*FT];
__device__ float g_v2[Hh*FT];
__device__ float g_u[BHN];
__device__ float g_E1[BHN];
__device__ float g_F1[BHN];
__device__ float g_vv[BHN];
__device__ float g_SE[BHN];
__device__ float g_SF[BHN];
__device__ float4 g_cf[BHN];            // (vv, c1, c2, 0)
__device__ uint32_t g_adjb[Bb*Nn*64];   // 2MB bitmask: bit j of word [b][i][j>>5]
__device__ float g_WhT[BH*Dd*Nn];       // 8MB: WhT[b][h][d][j] (K-contiguous)

// mma.sync tf32 m16n8k8 (sm_80+, works on plain sm_103 target)
#define MMA_TF32(d, a0,a1,a2,a3, b0,b1) \
  asm volatile("mma.sync.aligned.m16n8k8.row.col.f32.tf32.tf32.f32 " \
    "{%0,%1,%2,%3}, {%4,%5,%6,%7}, {%8,%9}, {%0,%1,%2,%3};" \
    : "+f"((d)[0]),"+f"((d)[1]),"+f"((d)[2]),"+f"((d)[3]) \
    : "r"(a0),"r"(a1),"r"(a2),"r"(a3),"r"(b0),"r"(b1))

// ---- K0: v1/v2 GEMVs over Wq/Wk with a ----
__global__ void k0_v(const float* __restrict__ Wq, const float* __restrict__ Wk,
                     const float* __restrict__ a){
  int idx = blockIdx.x*blockDim.x + threadIdx.x;
  if (idx >= Hh*FT) return;
  int h = idx / FT, f = idx - h*FT;
  const float* wq = Wq + (h*FT + f)*Dd;
  const float* wk = Wk + (h*FT + f)*Dd;
  const float* a1 = a + h*2*Dd;
  const float* a2 = a1 + Dd;
  float s1 = 0.f, s2 = 0.f;
  #pragma unroll
  for (int d = 0; d < Dd; d++){ s1 += wq[d]*a1[d]; s2 += wk[d]*a2[d]; }
  g_v1[idx] = s1; g_v2[idx] = s2;
}

__global__ void k_init(){
  int idx = blockIdx.x*blockDim.x + threadIdx.x;
  if (idx < BHN){ g_SE[idx] = 0.f; g_SF[idx] = 0.f; }
}

// ---- K_pack: adj (int) -> bitmask words ----
__global__ void __launch_bounds__(256) k_pack(const int* __restrict__ adj){
  int grow = (blockIdx.x*256 + threadIdx.x) >> 5;   // 0..8191  (b*2048+i)
  int lane = threadIdx.x & 31;
  const int* rp = adj + (size_t)grow*Nn;
  uint32_t* op = g_adjb + grow*64;
  #pragma unroll 4
  for (int w = 0; w < 64; w++){
    int v = rp[w*32 + lane];
    uint32_t m = __ballot_sync(0xffffffffu, v != 0);
    if (lane == 0) op[w] = m;
  }
}

// ---- K1: WhT[b,h,d,n] = sum_f x[b,n,f] * W[h,f,d] (transposed epilogue) ----
__global__ void __launch_bounds__(256) k1_wh(const float* __restrict__ x,
                                             const float* __restrict__ W){
  __shared__ float Xs[16][68];
  __shared__ float Ws[16][68];
  __shared__ float Ts[64][65];
  int m0 = blockIdx.x*64;
  int h  = blockIdx.y;
  int tid = threadIdx.x;
  int tx = tid & 15, ty = tid >> 4;
  int lm = tid >> 2;
  int lk = (tid & 3) * 4;
  int wkk = tid >> 4;
  int wc  = (tid & 15) * 4;
  float acc[4][4];
  #pragma unroll
  for (int i=0;i<4;i++)
    #pragma unroll
    for (int j=0;j<4;j++) acc[i][j]=0.f;

  for (int k0 = 0; k0 < Ff; k0 += 16){
    float4 xv = *(const float4*)&x[(m0+lm)*Ff + k0 + lk];
    Xs[lk+0][lm]=xv.x; Xs[lk+1][lm]=xv.y; Xs[lk+2][lm]=xv.z; Xs[lk+3][lm]=xv.w;
    *(float4*)&Ws[wkk][wc] = *(const float4*)&W[h*Ff*Dd + (k0+wkk)*Dd + wc];
    __syncthreads();
    #pragma unroll
    for (int k=0;k<16;k++){
      float4 a4 = *(float4*)&Xs[k][ty*4];
      float4 b4 = *(float4*)&Ws[k][tx*4];
      float av[4] = {a4.x,a4.y,a4.z,a4.w};
      float bv[4] = {b4.x,b4.y,b4.z,b4.w};
      #pragma unroll
      for (int i=0;i<4;i++)
        #pragma unroll
        for (int j=0;j<4;j++) acc[i][j] += av[i]*bv[j];
    }
    __syncthreads();
  }
  #pragma unroll
  for (int i=0;i<4;i++)
    #pragma unroll
    for (int j=0;j<4;j++) Ts[ty*4+i][tx*4+j] = acc[i][j];
  __syncthreads();
  int b  = m0 >> 11;
  int nb = m0 & (Nn-1);
  int bh = b*Hh + h;
  int dRow = tid >> 2;
  int colG = (tid & 3) * 16;
  float* dst = &g_WhT[((size_t)bh*Dd + dRow)*Nn + nb + colG];
  #pragma unroll
  for (int g=0; g<4; g++){
    float4 o;
    o.x = Ts[colG+g*4+0][dRow];
    o.y = Ts[colG+g*4+1][dRow];
    o.z = Ts[colG+g*4+2][dRow];
    o.w = Ts[colG+g*4+3][dRow];
    *(float4*)(dst + g*4) = o;
  }
}

// ---- K1b: e1/e2 GEMVs ----
__global__ void __launch_bounds__(256) k1b_e(const float* __restrict__ x,
                                             const float* __restrict__ toh){
  __shared__ float sv1[Hh*FT], sv2[Hh*FT];
  int tid = threadIdx.x;
  for (int i = tid; i < Hh*FT; i += 256){ sv1[i]=g_v1[i]; sv2[i]=g_v2[i]; }
  __syncthreads();
  int warp = tid >> 5, lane = tid & 31;
  int node = blockIdx.x*8 + warp;
  int b = node >> 11, n = node & (Nn-1);
  const float* xr = x + node*Ff;
  float aq[4]={0,0,0,0}, ak[4]={0,0,0,0};
  for (int f0 = 0; f0 < Ff; f0 += 32){
    float xv = xr[f0+lane];
    #pragma unroll
    for (int h=0;h<4;h++){
      aq[h] += xv * sv1[h*FT + f0 + lane];
      ak[h] += xv * sv2[h*FT + f0 + lane];
    }
  }
  if (lane < Tt){
    float tv = toh[node*Tt + lane];
    #pragma unroll
    for (int h=0;h<4;h++){
      aq[h] += tv * sv1[h*FT + Ff + lane];
      ak[h] += tv * sv2[h*FT + Ff + lane];
    }
  }
  #pragma unroll
  for (int off=16; off; off>>=1){
    #pragma unroll
    for (int h=0;h<4;h++){
      aq[h] += __shfl_xor_sync(0xffffffffu, aq[h], off);
      ak[h] += __shfl_xor_sync(0xffffffffu, ak[h], off);
    }
  }
  if (lane == 0){
    #pragma unroll
    for (int h=0;h<4;h++){
      int idx = (b*Hh + h)*Nn + n;
      g_u[idx]  = aq[h];
      g_E1[idx] = __expf(aq[h]);
      g_F1[idx] = __expf(0.2f*aq[h]);
      g_vv[idx] = ak[h];
    }
  }
}

// ---- K2: column stats via bitmask ----
__global__ void __launch_bounds__(256) k2_stats(){
  __shared__ float su[1024], sE[1024], sF[1024];
  __shared__ uint32_t sB[2048];   // [i 256][w 8]
  int tid = threadIdx.x;
  int jt = blockIdx.x, ic = blockIdx.y, b = blockIdx.z;
  int i0 = ic*256;
  for (int i = tid; i < 1024; i += 256){
    int h = i >> 8, ii = i & 255;
    int idx = (b*Hh + h)*Nn + i0 + ii;
    su[i] = g_u[idx]; sE[i] = g_E1[idx]; sF[i] = g_F1[idx];
  }
  for (int idx = tid; idx < 2048; idx += 256){
    int ii = idx >> 3, w = idx & 7;
    sB[idx] = g_adjb[(size_t)(b*Nn + i0 + ii)*64 + jt*8 + w];
  }
  __syncthreads();
  int j = jt*256 + tid;
  int jw = tid >> 5, jb = tid & 31;
  float v4[4], SEr[4]={0,0,0,0}, SFr[4]={0,0,0,0};
  #pragma unroll
  for (int h=0;h<4;h++) v4[h] = g_vv[(b*Hh+h)*Nn + j];
  #pragma unroll 4
  for (int ii = 0; ii < 256; ii++){
    uint32_t word = sB[ii*8 + jw];
    if ((word >> jb) & 1u){
      #pragma unroll
      for (int h=0;h<4;h++){
        bool pos = (su[h*256+ii] + v4[h]) > 0.f;
        SEr[h] += pos ? sE[h*256+ii] : 0.f;
        SFr[h] += pos ? 0.f : sF[h*256+ii];
      }
    }
  }
  #pragma unroll
  for (int h=0;h<4;h++){
    atomicAdd(&g_SE[(b*Hh+h)*Nn + j], SEr[h]);
    atomicAdd(&g_SF[(b*Hh+h)*Nn + j], SFr[h]);
  }
}

// ---- K2b: packed coefficients ----
__global__ void k2b_c(){
  int idx = blockIdx.x*blockDim.x + threadIdx.x;
  if (idx >= BHN) return;
  float v  = g_vv[idx];
  float ev = __expf(v), ef = __expf(0.2f*v);
  float den = ev*g_SE[idx] + ef*g_SF[idx];
  float inv = (den > 0.f) ? (1.f/den) : 0.f;
  g_cf[idx] = make_float4(v, ev*inv, ef*inv, 0.f);
}

// ---- K3: D[128,64] = P[128,2048] @ Wh[2048,64] via tf32 mma.sync ----
// 8 warps: 4(M) x 2(N); warp tile 32x32; A generated in registers from bitmask.
__global__ void __launch_bounds__(256) k3_mma(float* __restrict__ out){
  __shared__ float Bs[2][64*40];        // [d][k], pad 40: conflict-free frag loads
  __shared__ float4 scf[2][32];
  __shared__ uint32_t sAdj[2][128];
  int b = blockIdx.z, h = blockIdx.y, i0 = blockIdx.x*128;
  int bh = b*Hh + h;
  int tid = threadIdx.x, wid = tid>>5, lane = tid&31;
  int wm = wid >> 1, wn = wid & 1;
  int gid = lane >> 2, tig = lane & 3;

  float ui[4], Ei[4], Fi[4];
  #pragma unroll
  for (int q=0;q<4;q++){
    int idx = bh*Nn + i0 + wm*32 + gid + 8*q;
    ui[q] = g_u[idx]; Ei[q] = g_E1[idx]; Fi[q] = g_F1[idx];
  }
  int sd = tid >> 2, skg = (tid & 3) * 8;   // B staging role

  // prologue: stage chunk 0 into slot 0
  {
    const float* wp = &g_WhT[((size_t)bh*Dd + sd)*Nn + skg];
    float4 x0 = *(const float4*)wp, x1 = *(const float4*)(wp+4);
    float* bp = &Bs[0][sd*40 + skg];
    *(float4*)bp = x0; *(float4*)(bp+4) = x1;
    if (tid < 32) scf[0][tid] = g_cf[bh*Nn + tid];
    if (tid >= 64 && tid < 192) sAdj[0][tid-64] = g_adjb[(size_t)(b*Nn + i0 + tid-64)*64];
  }
  __syncthreads();

  float acc[2][4][4];
  #pragma unroll
  for (int mt=0;mt<2;mt++)
    #pragma unroll
    for (int nt=0;nt<4;nt++)
      #pragma unroll
      for (int e=0;e<4;e++) acc[mt][nt][e]=0.f;

  for (int c = 0; c < 64; ++c){
    int p = c & 1;
    if (c < 63){
      int s = p ^ 1, cn = c + 1;
      const float* wp = &g_WhT[((size_t)bh*Dd + sd)*Nn + cn*32 + skg];
      float4 x0 = *(const float4*)wp, x1 = *(const float4*)(wp+4);
      float* bp = &Bs[s][sd*40 + skg];
      *(float4*)bp = x0; *(float4*)(bp+4) = x1;
      if (tid < 32) scf[s][tid] = g_cf[bh*Nn + cn*32 + tid];
      if (tid >= 64 && tid < 192) sAdj[s][tid-64] = g_adjb[(size_t)(b*Nn + i0 + tid-64)*64 + cn];
    }
    uint32_t w4[4];
    #pragma unroll
    for (int q=0;q<4;q++) w4[q] = sAdj[p][wm*32 + gid + 8*q];

    #pragma unroll
    for (int ks = 0; ks < 4; ++ks){
      float4 coA = scf[p][ks*8 + tig];
      float4 coB = scf[p][ks*8 + tig + 4];
      int jlA = ks*8 + tig, jlB = jlA + 4;
      uint32_t bb[4][2];
      #pragma unroll
      for (int nt=0;nt<4;nt++){
        int n = wn*32 + nt*8 + gid;
        bb[nt][0] = __float_as_uint(Bs[p][n*40 + ks*8 + tig]);
        bb[nt][1] = __float_as_uint(Bs[p][n*40 + ks*8 + tig + 4]);
      }
      #pragma unroll
      for (int mt=0;mt<2;mt++){
        uint32_t a0,a1,a2,a3;
        {
          int q = 2*mt;
          float s0 = ui[q] + coA.x;
          float t0 = (s0 > 0.f) ? Ei[q]*coA.y : Fi[q]*coA.z;
          a0 = ((w4[q]>>jlA)&1u) ? __float_as_uint(t0) : 0u;
          float s2 = ui[q] + coB.x;
          float t2 = (s2 > 0.f) ? Ei[q]*coB.y : Fi[q]*coB.z;
          a2 = ((w4[q]>>jlB)&1u) ? __float_as_uint(t2) : 0u;
        }
        {
          int q = 2*mt+1;
          float s1 = ui[q] + coA.x;
          float t1 = (s1 > 0.f) ? Ei[q]*coA.y : Fi[q]*coA.z;
          a1 = ((w4[q]>>jlA)&1u) ? __float_as_uint(t1) : 0u;
          float s3 = ui[q] + coB.x;
          float t3 = (s3 > 0.f) ? Ei[q]*coB.y : Fi[q]*coB.z;
          a3 = ((w4[q]>>jlB)&1u) ? __float_as_uint(t3) : 0u;
        }
        MMA_TF32(acc[mt][0], a0,a1,a2,a3, bb[0][0], bb[0][1]);
        MMA_TF32(acc[mt][1], a0,a1,a2,a3, bb[1][0], bb[1][1]);
        MMA_TF32(acc[mt][2], a0,a1,a2,a3, bb[2][0], bb[2][1]);
        MMA_TF32(acc[mt][3], a0,a1,a2,a3, bb[3][0], bb[3][1]);
      }
    }
    __syncthreads();
  }

  // epilogue: ELU + store
  #pragma unroll
  for (int mt=0;mt<2;mt++){
    int r0 = i0 + wm*32 + 16*mt + gid;
    #pragma unroll
    for (int nt=0;nt<4;nt++){
      int d0 = h*Dd + wn*32 + nt*8 + tig*2;
      float t;
      float2 o01, o23;
      t = acc[mt][nt][0]; o01.x = (t > 0.f) ? t : (__expf(t)-1.f);
      t = acc[mt][nt][1]; o01.y = (t > 0.f) ? t : (__expf(t)-1.f);
      t = acc[mt][nt][2]; o23.x = (t > 0.f) ? t : (__expf(t)-1.f);
      t = acc[mt][nt][3]; o23.y = (t > 0.f) ? t : (__expf(t)-1.f);
      *(float2*)&out[(size_t)(b*Nn + r0    )*(Hh*Dd) + d0] = o01;
      *(float2*)&out[(size_t)(b*Nn + r0 + 8)*(Hh*Dd) + d0] = o23;
    }
  }
}

extern "C" void kernel_launch(void* const* d_in, const int* in_sizes, int n_in,
                              void* d_out, int out_size) {
  const float* x   = (const float*)d_in[0];  // (4,2048,256)
  const int*   adj = (const int*)  d_in[1];  // (4,2048,2048)
  const float* toh = (const float*)d_in[2];  // (4,2048,8)
  const float* Wq  = (const float*)d_in[3];  // (4,264,64)
  const float* Wk  = (const float*)d_in[4];  // (4,264,64)
  const float* W   = (const float*)d_in[5];  // (4,256,64)
  const float* a   = (const float*)d_in[6];  // (4,128,1)
  float* out = (float*)d_out;                // (4,2048,1024) fp32

  k0_v<<<5, 256>>>(Wq, Wk, a);
  k_init<<<128, 256>>>();
  k_pack<<<1024, 256>>>(adj);
  k1_wh<<<dim3(128, 4), 256>>>(x, W);
  k1b_e<<<1024, 256>>>(x, toh);
  k2_stats<<<dim3(8, 8, 4), 256>>>();
  k2b_c<<<128, 256>>>();
  k3_mma<<<dim3(16, Hh, Bb), 256>>>(out);
}

// round 9
// speedup vs baseline: 1.9621x; 1.0446x over previous
#include <cuda_runtime.h>
#include <cuda_bf16.h>
#include <cstdint>

#define Bb 4
#define Nn 2048
#define Ff 256
#define Tt 8
#define Hh 4
#define Dd 64
#define FT 264
#define BH (Bb*Hh)      // 16
#define BHN (BH*Nn)     // 32768

// ---- scratch (static device globals; no allocation) ----
__device__ float g_v1[Hh*FT];
__device__ float g_v2[Hh*FT];
__device__ float g_u[BHN];
__device__ float g_E1[BHN];
__device__ float g_F1[BHN];
__device__ float g_vv[BHN];
__device__ float g_SE[BHN];
__device__ float g_SF[BHN];
__device__ float4 g_cf[BHN];            // (vv, c1, c2, 0)
__device__ uint32_t g_adjb[Bb*Nn*64];   // 2MB bitmask
__device__ float g_Wh[BH*Nn*Dd];        // 8MB: Wh[bh][n][d], tf32-RN pre-rounded

// mma.sync tf32 m16n8k8 (sm_80+, plain sm_103 target OK)
#define MMA_TF32(d, a0,a1,a2,a3, b0,b1) \
  asm volatile("mma.sync.aligned.m16n8k8.row.col.f32.tf32.tf32.f32 " \
    "{%0,%1,%2,%3}, {%4,%5,%6,%7}, {%8,%9}, {%0,%1,%2,%3};" \
    : "+f"((d)[0]),"+f"((d)[1]),"+f"((d)[2]),"+f"((d)[3]) \
    : "r"(a0),"r"(a1),"r"(a2),"r"(a3),"r"(b0),"r"(b1))

__device__ __forceinline__ uint32_t tf32_rn_bits(float f){
  uint32_t u; asm("cvt.rna.tf32.f32 %0, %1;" : "=r"(u) : "f"(f)); return u;
}
__device__ __forceinline__ float tf32_rn(float f){
  return __uint_as_float(tf32_rn_bits(f));
}
__device__ __forceinline__ void tf32_split(float f, uint32_t& hi, uint32_t& lo){
  hi = tf32_rn_bits(f);
  float r = f - __uint_as_float(hi);
  lo = tf32_rn_bits(r);
}

// ---- K0: v1/v2 GEMVs + zero SE/SF (graph-replay safe) ----
__global__ void k0_init(const float* __restrict__ Wq, const float* __restrict__ Wk,
                        const float* __restrict__ a){
  int idx = blockIdx.x*blockDim.x + threadIdx.x;
  if (idx < BHN){ g_SE[idx] = 0.f; g_SF[idx] = 0.f; }
  if (idx >= Hh*FT) return;
  int h = idx / FT, f = idx - h*FT;
  const float* wq = Wq + (h*FT + f)*Dd;
  const float* wk = Wk + (h*FT + f)*Dd;
  const float* a1 = a + h*2*Dd;
  const float* a2 = a1 + Dd;
  float s1 = 0.f, s2 = 0.f;
  #pragma unroll
  for (int d = 0; d < Dd; d++){ s1 += wq[d]*a1[d]; s2 += wk[d]*a2[d]; }
  g_v1[idx] = s1; g_v2[idx] = s2;
}

// ---- K_pack: adj -> bitmask ----
__global__ void __launch_bounds__(256) k_pack(const int* __restrict__ adj){
  int grow = (blockIdx.x*256 + threadIdx.x) >> 5;
  int lane = threadIdx.x & 31;
  const int* rp = adj + (size_t)grow*Nn;
  uint32_t* op = g_adjb + grow*64;
  #pragma unroll 4
  for (int w = 0; w < 64; w++){
    int v = rp[w*32 + lane];
    uint32_t m = __ballot_sync(0xffffffffu, v != 0);
    if (lane == 0) op[w] = m;
  }
}

// ---- K1: Wh[bh][n][d] via tf32x3 mma.sync; fused e1/e2 GEMVs ----
// CTA: 128 rows x 64 cols, K=256 in 8 chunks of 32. 8 warps: 4(M)x2(N).
__global__ void __launch_bounds__(256) k1_wh(const float* __restrict__ x,
                                             const float* __restrict__ W,
                                             const float* __restrict__ toh){
  __shared__ float As[128*36];            // [m][k] pad 36
  __shared__ float Bs[32*72];             // [k][d] pad 72
  __shared__ float sv1[FT], sv2[FT];
  __shared__ float sdq[256], sdk[256];
  int bx = blockIdx.x, h = blockIdx.y, b = blockIdx.z;
  int m0 = bx*128;
  int bh = b*Hh + h;
  int tid = threadIdx.x, wid = tid>>5, lane = tid&31;
  int wm = wid>>1, wn = wid&1, gid = lane>>2, tig = lane&3;
  for (int i = tid; i < FT; i += 256){ sv1[i]=g_v1[h*FT+i]; sv2[i]=g_v2[h*FT+i]; }

  int am = tid>>1, akh = (tid&1)*16;      // A staging: row, k-half
  int bk = tid>>3, bd0 = (tid&7)*8;       // B staging: k row, d group
  const float* xrow = &x[((size_t)(b*Nn)+m0+am)*Ff];

  float acc[2][4][4];
  #pragma unroll
  for (int mt=0;mt<2;mt++)
    #pragma unroll
    for (int nt=0;nt<4;nt++)
      #pragma unroll
      for (int e=0;e<4;e++) acc[mt][nt][e]=0.f;
  float dq = 0.f, dk = 0.f;

  // register prefetch chunk 0
  float4 ra[4]; float4 rb0, rb1;
  #pragma unroll
  for (int q=0;q<4;q++) ra[q] = *(const float4*)&xrow[akh + q*4];
  {
    const float* wp = &W[((size_t)h*Ff + bk)*Dd + bd0];
    rb0 = *(const float4*)wp; rb1 = *(const float4*)(wp+4);
  }

  for (int c = 0; c < 8; ++c){
    __syncthreads();                       // prev compute done
    // store staged regs + accumulate e-dots
    #pragma unroll
    for (int q=0;q<4;q++){
      *(float4*)&As[am*36 + akh + q*4] = ra[q];
      int k = c*32 + akh + q*4;
      dq += ra[q].x*sv1[k+0] + ra[q].y*sv1[k+1] + ra[q].z*sv1[k+2] + ra[q].w*sv1[k+3];
      dk += ra[q].x*sv2[k+0] + ra[q].y*sv2[k+1] + ra[q].z*sv2[k+2] + ra[q].w*sv2[k+3];
    }
    *(float4*)&Bs[bk*72 + bd0]     = rb0;
    *(float4*)&Bs[bk*72 + bd0 + 4] = rb1;
    if (c < 7){
      #pragma unroll
      for (int q=0;q<4;q++) ra[q] = *(const float4*)&xrow[(c+1)*32 + akh + q*4];
      const float* wp = &W[((size_t)h*Ff + (c+1)*32 + bk)*Dd + bd0];
      rb0 = *(const float4*)wp; rb1 = *(const float4*)(wp+4);
    }
    __syncthreads();                       // staging visible
    #pragma unroll
    for (int ks = 0; ks < 4; ++ks){
      uint32_t ah[2][4], al[2][4];
      #pragma unroll
      for (int mt=0;mt<2;mt++){
        int r = wm*32 + 16*mt + gid;
        float f0 = As[r*36     + ks*8 + tig];
        float f1 = As[(r+8)*36 + ks*8 + tig];
        float f2 = As[r*36     + ks*8 + tig + 4];
        float f3 = As[(r+8)*36 + ks*8 + tig + 4];
        tf32_split(f0, ah[mt][0], al[mt][0]);
        tf32_split(f1, ah[mt][1], al[mt][1]);
        tf32_split(f2, ah[mt][2], al[mt][2]);
        tf32_split(f3, ah[mt][3], al[mt][3]);
      }
      uint32_t bhh[4][2], bll[4][2];
      #pragma unroll
      for (int nt=0;nt<4;nt++){
        int n = wn*32 + nt*8 + gid;
        float f0 = Bs[(ks*8+tig)*72 + n];
        float f1 = Bs[(ks*8+tig+4)*72 + n];
        tf32_split(f0, bhh[nt][0], bll[nt][0]);
        tf32_split(f1, bhh[nt][1], bll[nt][1]);
      }
      #pragma unroll
      for (int mt=0;mt<2;mt++)
        #pragma unroll
        for (int nt=0;nt<4;nt++){
          MMA_TF32(acc[mt][nt], ah[mt][0],ah[mt][1],ah[mt][2],ah[mt][3], bhh[nt][0],bhh[nt][1]);
          MMA_TF32(acc[mt][nt], ah[mt][0],ah[mt][1],ah[mt][2],ah[mt][3], bll[nt][0],bll[nt][1]);
          MMA_TF32(acc[mt][nt], al[mt][0],al[mt][1],al[mt][2],al[mt][3], bhh[nt][0],bhh[nt][1]);
        }
    }
  }
  // toh tail (odd thread of each row pair)
  if (akh == 16){
    const float* tp = &toh[((size_t)(b*Nn)+m0+am)*Tt];
    #pragma unroll
    for (int t=0;t<8;t++){ float tv = tp[t]; dq += tv*sv1[Ff+t]; dk += tv*sv2[Ff+t]; }
  }
  sdq[tid] = dq; sdk[tid] = dk;
  __syncthreads();
  if (tid < 128){
    float q  = sdq[tid*2] + sdq[tid*2+1];
    float kk = sdk[tid*2] + sdk[tid*2+1];
    int idx = bh*Nn + m0 + tid;
    g_u[idx]  = q;
    g_E1[idx] = __expf(q);
    g_F1[idx] = __expf(0.2f*q);
    g_vv[idx] = kk;
  }
  // Wh epilogue: tf32-RN pre-rounded store
  #pragma unroll
  for (int mt=0;mt<2;mt++){
    int r = m0 + wm*32 + 16*mt + gid;
    #pragma unroll
    for (int nt=0;nt<4;nt++){
      int col = wn*32 + nt*8 + tig*2;
      float2 v0, v1;
      v0.x = tf32_rn(acc[mt][nt][0]); v0.y = tf32_rn(acc[mt][nt][1]);
      v1.x = tf32_rn(acc[mt][nt][2]); v1.y = tf32_rn(acc[mt][nt][3]);
      *(float2*)&g_Wh[((size_t)bh*Nn + r)*Dd + col]     = v0;
      *(float2*)&g_Wh[((size_t)bh*Nn + r + 8)*Dd + col] = v1;
    }
  }
}

// ---- K2: column stats (float4-packed smem, branchless) ----
__global__ void __launch_bounds__(256) k2_stats(){
  __shared__ float4 sPack[1024];          // [h][ii] = (u, E, F, 0)
  __shared__ uint32_t sB[2048];           // [ii][w]
  int tid = threadIdx.x;
  int jt = blockIdx.x, ic = blockIdx.y, b = blockIdx.z;
  int i0 = ic*256;
  for (int i = tid; i < 1024; i += 256){
    int h = i >> 8, ii = i & 255;
    int idx = (b*Hh + h)*Nn + i0 + ii;
    sPack[i] = make_float4(g_u[idx], g_E1[idx], g_F1[idx], 0.f);
  }
  for (int idx = tid; idx < 2048; idx += 256){
    int ii = idx >> 3, w = idx & 7;
    sB[idx] = g_adjb[(size_t)(b*Nn + i0 + ii)*64 + jt*8 + w];
  }
  __syncthreads();
  int j = jt*256 + tid;
  int jw = tid >> 5, jb = tid & 31;
  float nv[4], SEr[4]={0,0,0,0}, SFr[4]={0,0,0,0};
  #pragma unroll
  for (int h=0;h<4;h++) nv[h] = -g_vv[(b*Hh+h)*Nn + j];
  #pragma unroll 2
  for (int ii = 0; ii < 256; ii++){
    uint32_t word = sB[ii*8 + jw];
    float bf = (float)((word >> jb) & 1u);
    #pragma unroll
    for (int h=0;h<4;h++){
      float4 pk = sPack[h*256 + ii];
      bool pos = pk.x > nv[h];
      SEr[h] += bf * (pos ? pk.y : 0.f);
      SFr[h] += bf * (pos ? 0.f : pk.z);
    }
  }
  #pragma unroll
  for (int h=0;h<4;h++){
    atomicAdd(&g_SE[(b*Hh+h)*Nn + j], SEr[h]);
    atomicAdd(&g_SF[(b*Hh+h)*Nn + j], SFr[h]);
  }
}

// ---- K2b: packed coefficients ----
__global__ void k2b_c(){
  int idx = blockIdx.x*blockDim.x + threadIdx.x;
  if (idx >= BHN) return;
  float v  = g_vv[idx];
  float ev = __expf(v), ef = __expf(0.2f*v);
  float den = ev*g_SE[idx] + ef*g_SF[idx];
  float inv = (den > 0.f) ? (1.f/den) : 0.f;
  g_cf[idx] = make_float4(v, ev*inv, ef*inv, 0.f);
}

// ---- K3: out = elu(P @ Wh) via tf32 mma.sync; P generated in registers ----
__global__ void __launch_bounds__(256) k3_mma(float* __restrict__ out){
  __shared__ float Bs[2][32*72];          // [k(j)][d] pad 72, conflict-free
  __shared__ float4 scf[2][32];
  __shared__ uint32_t sAdj[2][128];
  int b = blockIdx.z, h = blockIdx.y, i0 = blockIdx.x*128;
  int bh = b*Hh + h;
  int tid = threadIdx.x, wid = tid>>5, lane = tid&31;
  int wm = wid >> 1, wn = wid & 1;
  int gid = lane >> 2, tig = lane & 3;

  float ui[4], Ei[4], Fi[4];
  #pragma unroll
  for (int q=0;q<4;q++){
    int idx = bh*Nn + i0 + wm*32 + gid + 8*q;
    ui[q] = g_u[idx]; Ei[q] = g_E1[idx]; Fi[q] = g_F1[idx];
  }
  int sj = tid >> 3, sd0 = (tid & 7) * 8;  // B staging role

  // prologue: stage chunk 0 into slot 0
  {
    const float* wp = &g_Wh[((size_t)bh*Nn + sj)*Dd + sd0];
    float4 x0 = *(const float4*)wp, x1 = *(const float4*)(wp+4);
    *(float4*)&Bs[0][sj*72 + sd0]     = x0;
    *(float4*)&Bs[0][sj*72 + sd0 + 4] = x1;
    if (tid < 32) scf[0][tid] = g_cf[bh*Nn + tid];
    if (tid >= 64 && tid < 192) sAdj[0][tid-64] = g_adjb[(size_t)(b*Nn + i0 + tid-64)*64];
  }
  __syncthreads();

  float acc[2][4][4];
  #pragma unroll
  for (int mt=0;mt<2;mt++)
    #pragma unroll
    for (int nt=0;nt<4;nt++)
      #pragma unroll
      for (int e=0;e<4;e++) acc[mt][nt][e]=0.f;

  for (int c = 0; c < 64; ++c){
    int p = c & 1;
    if (c < 63){
      int s = p ^ 1, cn = c + 1;
      const float* wp = &g_Wh[((size_t)bh*Nn + cn*32 + sj)*Dd + sd0];
      float4 x0 = *(const float4*)wp, x1 = *(const float4*)(wp+4);
      *(float4*)&Bs[s][sj*72 + sd0]     = x0;
      *(float4*)&Bs[s][sj*72 + sd0 + 4] = x1;
      if (tid < 32) scf[s][tid] = g_cf[bh*Nn + cn*32 + tid];
      if (tid >= 64 && tid < 192) sAdj[s][tid-64] = g_adjb[(size_t)(b*Nn + i0 + tid-64)*64 + cn];
    }
    uint32_t w4[4];
    #pragma unroll
    for (int q=0;q<4;q++) w4[q] = sAdj[p][wm*32 + gid + 8*q];

    #pragma unroll
    for (int ks = 0; ks < 4; ++ks){
      float4 coA = scf[p][ks*8 + tig];
      float4 coB = scf[p][ks*8 + tig + 4];
      int jlA = ks*8 + tig, jlB = jlA + 4;
      uint32_t bb[4][2];
      #pragma unroll
      for (int nt=0;nt<4;nt++){
        int n = wn*32 + nt*8 + gid;
        bb[nt][0] = __float_as_uint(Bs[p][(ks*8+tig)*72 + n]);
        bb[nt][1] = __float_as_uint(Bs[p][(ks*8+tig+4)*72 + n]);
      }
      #pragma unroll
      for (int mt=0;mt<2;mt++){
        uint32_t a0,a1,a2,a3;
        {
          int q = 2*mt;
          float s0 = ui[q] + coA.x;
          float t0 = (s0 > 0.f) ? Ei[q]*coA.y : Fi[q]*coA.z;
          a0 = ((w4[q]>>jlA)&1u) ? tf32_rn_bits(t0) : 0u;
          float s2 = ui[q] + coB.x;
          float t2 = (s2 > 0.f) ? Ei[q]*coB.y : Fi[q]*coB.z;
          a2 = ((w4[q]>>jlB)&1u) ? tf32_rn_bits(t2) : 0u;
        }
        {
          int q = 2*mt+1;
          float s1 = ui[q] + coA.x;
          float t1 = (s1 > 0.f) ? Ei[q]*coA.y : Fi[q]*coA.z;
          a1 = ((w4[q]>>jlA)&1u) ? tf32_rn_bits(t1) : 0u;
          float s3 = ui[q] + coB.x;
          float t3 = (s3 > 0.f) ? Ei[q]*coB.y : Fi[q]*coB.z;
          a3 = ((w4[q]>>jlB)&1u) ? tf32_rn_bits(t3) : 0u;
        }
        MMA_TF32(acc[mt][0], a0,a1,a2,a3, bb[0][0], bb[0][1]);
        MMA_TF32(acc[mt][1], a0,a1,a2,a3, bb[1][0], bb[1][1]);
        MMA_TF32(acc[mt][2], a0,a1,a2,a3, bb[2][0], bb[2][1]);
        MMA_TF32(acc[mt][3], a0,a1,a2,a3, bb[3][0], bb[3][1]);
      }
    }
    __syncthreads();
  }

  // epilogue: ELU + store
  #pragma unroll
  for (int mt=0;mt<2;mt++){
    int r0 = i0 + wm*32 + 16*mt + gid;
    #pragma unroll
    for (int nt=0;nt<4;nt++){
      int d0 = h*Dd + wn*32 + nt*8 + tig*2;
      float t;
      float2 o01, o23;
      t = acc[mt][nt][0]; o01.x = (t > 0.f) ? t : (__expf(t)-1.f);
      t = acc[mt][nt][1]; o01.y = (t > 0.f) ? t : (__expf(t)-1.f);
      t = acc[mt][nt][2]; o23.x = (t > 0.f) ? t : (__expf(t)-1.f);
      t = acc[mt][nt][3]; o23.y = (t > 0.f) ? t : (__expf(t)-1.f);
      *(float2*)&out[(size_t)(b*Nn + r0    )*(Hh*Dd) + d0] = o01;
      *(float2*)&out[(size_t)(b*Nn + r0 + 8)*(Hh*Dd) + d0] = o23;
    }
  }
}

extern "C" void kernel_launch(void* const* d_in, const int* in_sizes, int n_in,
                              void* d_out, int out_size) {
  const float* x   = (const float*)d_in[0];  // (4,2048,256)
  const int*   adj = (const int*)  d_in[1];  // (4,2048,2048)
  const float* toh = (const float*)d_in[2];  // (4,2048,8)
  const float* Wq  = (const float*)d_in[3];  // (4,264,64)
  const float* Wk  = (const float*)d_in[4];  // (4,264,64)
  const float* W   = (const float*)d_in[5];  // (4,256,64)
  const float* a   = (const float*)d_in[6];  // (4,128,1)
  float* out = (float*)d_out;                // (4,2048,1024) fp32

  k0_init<<<128, 256>>>(Wq, Wk, a);
  k_pack<<<1024, 256>>>(adj);
  k1_wh<<<dim3(16, Hh, Bb), 256>>>(x, W, toh);
  k2_stats<<<dim3(8, 8, 4), 256>>>();
  k2b_c<<<128, 256>>>();
  k3_mma<<<dim3(16, Hh, Bb), 256>>>(out);
}